// round 14
// baseline (speedup 1.0000x reference)
#include <cuda_runtime.h>
#include <cuda_fp16.h>
#include <cstdint>
#include <math.h>

// Causal GQA attention prefill, S=2048, H=32, KVH=8, D=128, fp32 I/O.
// Pure fp16 mma.sync. Pre-pass converts K/V to fp16 (V transposed+packed).
// BM=128, 32 rows/warp, P in registers, cp.async double-buffered K/V.
// R14: R12 structure + (a) whole-tile causal skip (no inner guards),
// (b) data-dependent O-rescale skip when alpha == 1.0 (bit-identical).

#define NH    32
#define NKVH  8
#define HD    128
#define BM    128
#define BN    64
#define SMAX  2048
#define QK_SCALE 0.08838834764831845f
#define LOG2E    1.4426950408889634f

#define QKSTR 68   // Q/K row stride in u32 words (64 data + 4 pad)
#define VSTR  36   // VT row stride in u32 words (32 data + 4 pad)

#define SM_Q  0                       // Q  [128][68] u32 = 34816 B
#define SM_K0 34816                   // K0 [64][68]  u32 = 17408 B
#define SM_K1 52224                   // K1
#define SM_V0 69632                   // V0 [128][36] u32 = 18432 B
#define SM_V1 88064                   // V1
#define SMEM_BYTES 106496

// fp16 scratch (pre-converted). K: [s][kvh][64 d-pairs]. V: [kvh][kt][d][32 kv-pairs].
__device__ uint32_t Kh_g[SMAX * NKVH * 64];
__device__ uint32_t VT_g[NKVH * (SMAX / BN) * HD * 32];

__device__ __forceinline__ uint32_t smem_u32(const void* p) {
    uint32_t a;
    asm("{ .reg .u64 t; cvta.to.shared.u64 t, %1; cvt.u32.u64 %0, t; }" : "=r"(a) : "l"(p));
    return a;
}
__device__ __forceinline__ float ex2(float x) {
    float r; asm("ex2.approx.f32 %0, %1;" : "=f"(r) : "f"(x)); return r;
}
__device__ __forceinline__ uint32_t pack_f16x2(float lo, float hi) {
    uint32_t r; asm("cvt.rn.f16x2.f32 %0, %1, %2;" : "=r"(r) : "f"(hi), "f"(lo)); return r;
}

#define MMA_F16(c, a, b) \
    asm volatile("mma.sync.aligned.m16n8k16.row.col.f32.f16.f16.f32 " \
                 "{%0,%1,%2,%3},{%4,%5,%6,%7},{%8,%9},{%0,%1,%2,%3};" \
        : "+f"((c)[0]), "+f"((c)[1]), "+f"((c)[2]), "+f"((c)[3]) \
        : "r"((a)[0]), "r"((a)[1]), "r"((a)[2]), "r"((a)[3]), "r"((b)[0]), "r"((b)[1]))

#define LDMX4(r, addr) \
    asm volatile("ldmatrix.sync.aligned.m8n8.x4.shared.b16 {%0,%1,%2,%3}, [%4];" \
        : "=r"((r)[0]), "=r"((r)[1]), "=r"((r)[2]), "=r"((r)[3]) : "r"(addr))

#define STSV2(addr, r0, r1) \
    asm volatile("st.shared.v2.b32 [%0], {%1,%2};" :: "r"(addr), "r"(r0), "r"(r1) : "memory")

#define CPASYNC16(dst, src) \
    asm volatile("cp.async.cg.shared.global [%0], [%1], 16;" :: "r"(dst), "l"(src) : "memory")
#define CPASYNC_COMMIT() asm volatile("cp.async.commit_group;" ::: "memory")
#define CPASYNC_WAIT0()  asm volatile("cp.async.wait_group 0;" ::: "memory")

// ---- pre-pass 1: K fp32 -> fp16 packed, linear (fully coalesced) ----
__global__ void convert_k_kernel(const float* __restrict__ k, int n_pairs)
{
    int i = blockIdx.x * blockDim.x + threadIdx.x;
    if (i < n_pairs) {
        float2 val = reinterpret_cast<const float2*>(k)[i];
        Kh_g[i] = pack_f16x2(val.x, val.y);
    }
}

// ---- pre-pass 2: V fp32 -> fp16 transposed + kv-pair packed ----
__global__ void convert_v_kernel(const float* __restrict__ v)
{
    __shared__ float vs[64][129];
    const int kt = blockIdx.x, kvh = blockIdx.y, nkt = gridDim.x;
    const int tid = threadIdx.x;

    #pragma unroll
    for (int it = 0; it < 16; ++it) {
        const int idx = tid + it * 128;
        const int row = idx >> 5, f4 = idx & 31;
        float4 val = *reinterpret_cast<const float4*>(
            v + ((size_t)((kt * 64 + row) * NKVH + kvh)) * HD + f4 * 4);
        vs[row][f4 * 4 + 0] = val.x; vs[row][f4 * 4 + 1] = val.y;
        vs[row][f4 * 4 + 2] = val.z; vs[row][f4 * 4 + 3] = val.w;
    }
    __syncthreads();

    const int d = tid;
    uint32_t* outp = VT_g + ((size_t)(kvh * nkt + kt) * HD + d) * 32;
    #pragma unroll
    for (int p = 0; p < 32; ++p)
        outp[p] = pack_f16x2(vs[2 * p][d], vs[2 * p + 1][d]);
}

extern __shared__ unsigned char smem_raw[];

__global__ __launch_bounds__(128, 2)
void attn_mma_kernel(const float* __restrict__ q, float* __restrict__ out, int seq)
{
    const uint32_t sb  = smem_u32(smem_raw);
    const uint32_t q_b = sb + SM_Q;
    const uint32_t k_b[2] = { sb + SM_K0, sb + SM_K1 };
    const uint32_t v_b[2] = { sb + SM_V0, sb + SM_V1 };

    const int tid  = threadIdx.x;
    const int lane = tid & 31;
    const int wid  = tid >> 5;           // warp owns rows wid*32 .. wid*32+31
    const int g    = lane >> 2;
    const int tg   = lane & 3;

    const int qt  = (gridDim.x - 1) - blockIdx.x;   // heavy blocks first
    const int hh  = blockIdx.y;
    const int kvh = hh >> 2;
    const int q0  = qt * BM;
    const int nkt = seq >> 6;                       // 64-wide kv tiles total
    const int nkt_this = (qt + 1) * (BM / BN);      // kv tiles needed
    const int r_last = q0 + wid * 32 + 31;          // warp's last (largest) row

    // fill coords
    const int f_kv = tid >> 1;
    const int f_dp = (tid & 1) * 32;

    // ---- Q fill (once): fp32 gmem -> fp16 smem, scale*log2e folded ----
    {
        const float4* gq = reinterpret_cast<const float4*>(
            q + ((size_t)(q0 + tid) * NH + hh) * HD);
        const float sc = QK_SCALE * LOG2E;
        #pragma unroll
        for (int j = 0; j < 32; ++j) {
            float4 val = gq[j];
            const uint32_t off = (uint32_t)(tid * QKSTR + j * 2) * 4u;
            STSV2(q_b + off, pack_f16x2(val.x * sc, val.y * sc),
                             pack_f16x2(val.z * sc, val.w * sc));
        }
    }

    // ---- async prefetch of K/V tile kt into buffer bsel ----
    auto prefetch_kv = [&](int kt, int bsel) {
        const uint32_t* srcK =
            Kh_g + ((size_t)(kt * BN + f_kv) * NKVH + kvh) * 64 + f_dp;
        const uint32_t dstK = k_b[bsel] + (uint32_t)(f_kv * QKSTR + f_dp) * 4u;
        #pragma unroll
        for (int j = 0; j < 8; ++j)
            CPASYNC16(dstK + j * 16u, srcK + j * 4);
        const uint32_t* srcV =
            VT_g + ((size_t)(kvh * nkt + kt) * HD + tid) * 32;
        const uint32_t dstV = v_b[bsel] + (uint32_t)(tid * VSTR) * 4u;
        #pragma unroll
        for (int j = 0; j < 8; ++j)
            CPASYNC16(dstV + j * 16u, srcV + j * 4);
    };

    prefetch_kv(0, 0);
    CPASYNC_COMMIT();

    // Per-thread rows: mt in {0,1}, hb in {0,1} -> row wid*32 + mt*16 + g + hb*8
    float m_s[2][2] = { { -INFINITY, -INFINITY }, { -INFINITY, -INFINITY } };
    float l_s[2][2] = { { 0.f, 0.f }, { 0.f, 0.f } };
    float o[2][16][4];
    #pragma unroll
    for (int mt = 0; mt < 2; ++mt)
        #pragma unroll
        for (int nt = 0; nt < 16; ++nt)
            #pragma unroll
            for (int j = 0; j < 4; ++j) o[mt][nt][j] = 0.f;

    for (int kt = 0; kt < nkt_this; ++kt) {
        CPASYNC_WAIT0();     // tile kt copy complete (this thread)
        __syncthreads();     // all threads' copies visible; prev compute done

        // overlap: start copying tile kt+1 into the other buffer
        if (kt + 1 < nkt_this) {
            prefetch_kv(kt + 1, (kt + 1) & 1);
            CPASYNC_COMMIT();
        }
        const uint32_t kb = k_b[kt & 1];
        const uint32_t vb = v_b[kt & 1];
        const int ct = kt * BN;          // first kv col of this tile

        // Whole-tile causal skip (warp-uniform, bit-identical: skipped tiles
        // produce only exact zeros). No inner-loop guards (R13 lesson).
        if (ct > r_last) continue;

        // ---- gemm1: S = Q * K^T (fp16, warp: 32x64) ----
        float c1[2][8][4];
        #pragma unroll
        for (int mt = 0; mt < 2; ++mt)
            #pragma unroll
            for (int nt = 0; nt < 8; ++nt)
                #pragma unroll
                for (int j = 0; j < 4; ++j) c1[mt][nt][j] = 0.f;

        #pragma unroll
        for (int kc = 0; kc < 8; ++kc) {
            uint32_t aH[2][4], bH[8][2];
            #pragma unroll
            for (int mt = 0; mt < 2; ++mt) {
                const uint32_t offA = (uint32_t)((wid * 32 + mt * 16 + (lane & 15)) * QKSTR
                                                 + kc * 8 + (lane >> 4) * 4) * 4u;
                LDMX4(aH[mt], q_b + offA);
            }
            #pragma unroll
            for (int t = 0; t < 4; ++t) {
                const uint32_t offB = (uint32_t)((t * 16 + ((lane >> 4) & 1) * 8 + (lane & 7)) * QKSTR
                                                 + kc * 8 + ((lane >> 3) & 1) * 4) * 4u;
                uint32_t rh[4];
                LDMX4(rh, kb + offB);
                bH[2*t][0] = rh[0]; bH[2*t][1] = rh[1]; bH[2*t+1][0] = rh[2]; bH[2*t+1][1] = rh[3];
            }
            #pragma unroll
            for (int mt = 0; mt < 2; ++mt)
                #pragma unroll
                for (int nt = 0; nt < 8; ++nt)
                    MMA_F16(c1[mt][nt], aH[mt], bH[nt]);
        }

        // ---- mask (partial tiles) + online softmax (rows warp-local) ----
        const bool need_mask = (ct + BN - 1) > (q0 + wid * 32);
        #pragma unroll
        for (int mt = 0; mt < 2; ++mt) {
            #pragma unroll
            for (int hb = 0; hb < 2; ++hb) {
                const int qi = q0 + wid * 32 + mt * 16 + g + hb * 8;
                if (need_mask) {
                    #pragma unroll
                    for (int nt = 0; nt < 8; ++nt) {
                        const int kj = ct + nt * 8 + 2 * tg;
                        if (kj + 0 > qi) c1[mt][nt][hb * 2 + 0] = -INFINITY;
                        if (kj + 1 > qi) c1[mt][nt][hb * 2 + 1] = -INFINITY;
                    }
                }
                float mx = -INFINITY;
                #pragma unroll
                for (int nt = 0; nt < 8; ++nt)
                    mx = fmaxf(mx, fmaxf(c1[mt][nt][hb * 2], c1[mt][nt][hb * 2 + 1]));
                mx = fmaxf(mx, __shfl_xor_sync(0xffffffffu, mx, 1));
                mx = fmaxf(mx, __shfl_xor_sync(0xffffffffu, mx, 2));

                float rs = 0.f;
                if (mx > m_s[mt][hb]) {
                    // Row max grew: recompute P against new max, rescale O.
                    const float m_new = mx;
                    const float alpha = ex2(m_s[mt][hb] - m_new);  // 0 on first tile
                    m_s[mt][hb] = m_new;
                    #pragma unroll
                    for (int nt = 0; nt < 8; ++nt) {
                        float p0 = ex2(c1[mt][nt][hb * 2 + 0] - m_new);
                        float p1 = ex2(c1[mt][nt][hb * 2 + 1] - m_new);
                        c1[mt][nt][hb * 2 + 0] = p0;
                        c1[mt][nt][hb * 2 + 1] = p1;
                        rs += p0 + p1;
                    }
                    l_s[mt][hb] *= alpha;
                    #pragma unroll
                    for (int nt = 0; nt < 16; ++nt) {
                        o[mt][nt][hb * 2 + 0] *= alpha;
                        o[mt][nt][hb * 2 + 1] *= alpha;
                    }
                } else {
                    // alpha == 1.0 exactly: skip O rescale (bit-identical).
                    const float m_new = m_s[mt][hb];
                    #pragma unroll
                    for (int nt = 0; nt < 8; ++nt) {
                        float p0 = ex2(c1[mt][nt][hb * 2 + 0] - m_new);
                        float p1 = ex2(c1[mt][nt][hb * 2 + 1] - m_new);
                        c1[mt][nt][hb * 2 + 0] = p0;
                        c1[mt][nt][hb * 2 + 1] = p1;
                        rs += p0 + p1;
                    }
                }
                rs += __shfl_xor_sync(0xffffffffu, rs, 1);
                rs += __shfl_xor_sync(0xffffffffu, rs, 2);
                l_s[mt][hb] += rs;
            }
        }

        // ---- gemm2: O += P V. P packed from c1 registers; V frags shared by mt ----
        #pragma unroll
        for (int kc = 0; kc < 4; ++kc) {
            uint32_t aP[2][4];
            #pragma unroll
            for (int mt = 0; mt < 2; ++mt) {
                aP[mt][0] = pack_f16x2(c1[mt][2*kc+0][0], c1[mt][2*kc+0][1]);
                aP[mt][1] = pack_f16x2(c1[mt][2*kc+0][2], c1[mt][2*kc+0][3]);
                aP[mt][2] = pack_f16x2(c1[mt][2*kc+1][0], c1[mt][2*kc+1][1]);
                aP[mt][3] = pack_f16x2(c1[mt][2*kc+1][2], c1[mt][2*kc+1][3]);
            }
            #pragma unroll
            for (int t = 0; t < 8; ++t) {
                const uint32_t offV = (uint32_t)((t * 16 + ((lane >> 4) & 1) * 8 + (lane & 7)) * VSTR
                                                 + kc * 8 + ((lane >> 3) & 1) * 4) * 4u;
                uint32_t rv[4];
                LDMX4(rv, vb + offV);
                uint32_t b0[2] = { rv[0], rv[1] }, b1[2] = { rv[2], rv[3] };
                #pragma unroll
                for (int mt = 0; mt < 2; ++mt) {
                    MMA_F16(o[mt][2 * t + 0], aP[mt], b0);
                    MMA_F16(o[mt][2 * t + 1], aP[mt], b1);
                }
            }
        }
    }

    // ---- Epilogue: normalize, store ----
    #pragma unroll
    for (int mt = 0; mt < 2; ++mt)
        #pragma unroll
        for (int hb = 0; hb < 2; ++hb) {
            const float inv = 1.f / l_s[mt][hb];
            const int grow = q0 + wid * 32 + mt * 16 + g + hb * 8;
            float* obase = out + ((size_t)grow * NH + hh) * HD + 2 * tg;
            #pragma unroll
            for (int nt = 0; nt < 16; ++nt) {
                float2 val = make_float2(o[mt][nt][hb * 2 + 0] * inv,
                                         o[mt][nt][hb * 2 + 1] * inv);
                *reinterpret_cast<float2*>(obase + nt * 8) = val;
            }
        }
}

extern "C" void kernel_launch(void* const* d_in, const int* in_sizes, int n_in,
                              void* d_out, int out_size)
{
    const float* q = (const float*)d_in[0];
    const float* k = (const float*)d_in[1];
    const float* v = (const float*)d_in[2];
    float* out = (float*)d_out;

    const int seq = in_sizes[0] / (NH * HD);

    const int n_pairs = seq * NKVH * 64;
    convert_k_kernel<<<(n_pairs + 255) / 256, 256>>>(k, n_pairs);
    convert_v_kernel<<<dim3(seq / BN, NKVH), 128>>>(v);

    cudaFuncSetAttribute(attn_mma_kernel,
                         cudaFuncAttributeMaxDynamicSharedMemorySize, SMEM_BYTES);

    dim3 grid(seq / BM, NH);
    attn_mma_kernel<<<grid, 128, SMEM_BYTES>>>(q, out, seq);
}

// round 15
// speedup vs baseline: 1.0076x; 1.0076x over previous
#include <cuda_runtime.h>
#include <cuda_fp16.h>
#include <cstdint>
#include <math.h>

// Causal GQA attention prefill, S=2048, H=32, KVH=8, D=128, fp32 I/O.
// Pure fp16 mma.sync. Pre-pass converts K/V to fp16 (V transposed+packed).
// BM=128, 32 rows/warp, P in registers, cp.async double-buffered K/V.
// R15 = exact R12 + warp-ballot-guarded O-rescale (skip is bit-identical:
// when no lane's row-max grew, alpha==1.0 exactly for all lanes).

#define NH    32
#define NKVH  8
#define HD    128
#define BM    128
#define BN    64
#define SMAX  2048
#define QK_SCALE 0.08838834764831845f
#define LOG2E    1.4426950408889634f

#define QKSTR 68   // Q/K row stride in u32 words (64 data + 4 pad)
#define VSTR  36   // VT row stride in u32 words (32 data + 4 pad)

#define SM_Q  0                       // Q  [128][68] u32 = 34816 B
#define SM_K0 34816                   // K0 [64][68]  u32 = 17408 B
#define SM_K1 52224                   // K1
#define SM_V0 69632                   // V0 [128][36] u32 = 18432 B
#define SM_V1 88064                   // V1
#define SMEM_BYTES 106496

// fp16 scratch (pre-converted). K: [s][kvh][64 d-pairs]. V: [kvh][kt][d][32 kv-pairs].
__device__ uint32_t Kh_g[SMAX * NKVH * 64];
__device__ uint32_t VT_g[NKVH * (SMAX / BN) * HD * 32];

__device__ __forceinline__ uint32_t smem_u32(const void* p) {
    uint32_t a;
    asm("{ .reg .u64 t; cvta.to.shared.u64 t, %1; cvt.u32.u64 %0, t; }" : "=r"(a) : "l"(p));
    return a;
}
__device__ __forceinline__ float ex2(float x) {
    float r; asm("ex2.approx.f32 %0, %1;" : "=f"(r) : "f"(x)); return r;
}
__device__ __forceinline__ uint32_t pack_f16x2(float lo, float hi) {
    uint32_t r; asm("cvt.rn.f16x2.f32 %0, %1, %2;" : "=r"(r) : "f"(hi), "f"(lo)); return r;
}

#define MMA_F16(c, a, b) \
    asm volatile("mma.sync.aligned.m16n8k16.row.col.f32.f16.f16.f32 " \
                 "{%0,%1,%2,%3},{%4,%5,%6,%7},{%8,%9},{%0,%1,%2,%3};" \
        : "+f"((c)[0]), "+f"((c)[1]), "+f"((c)[2]), "+f"((c)[3]) \
        : "r"((a)[0]), "r"((a)[1]), "r"((a)[2]), "r"((a)[3]), "r"((b)[0]), "r"((b)[1]))

#define LDMX4(r, addr) \
    asm volatile("ldmatrix.sync.aligned.m8n8.x4.shared.b16 {%0,%1,%2,%3}, [%4];" \
        : "=r"((r)[0]), "=r"((r)[1]), "=r"((r)[2]), "=r"((r)[3]) : "r"(addr))

#define STSV2(addr, r0, r1) \
    asm volatile("st.shared.v2.b32 [%0], {%1,%2};" :: "r"(addr), "r"(r0), "r"(r1) : "memory")

#define CPASYNC16(dst, src) \
    asm volatile("cp.async.cg.shared.global [%0], [%1], 16;" :: "r"(dst), "l"(src) : "memory")
#define CPASYNC_COMMIT() asm volatile("cp.async.commit_group;" ::: "memory")
#define CPASYNC_WAIT0()  asm volatile("cp.async.wait_group 0;" ::: "memory")

// ---- pre-pass 1: K fp32 -> fp16 packed, linear (fully coalesced) ----
__global__ void convert_k_kernel(const float* __restrict__ k, int n_pairs)
{
    int i = blockIdx.x * blockDim.x + threadIdx.x;
    if (i < n_pairs) {
        float2 val = reinterpret_cast<const float2*>(k)[i];
        Kh_g[i] = pack_f16x2(val.x, val.y);
    }
}

// ---- pre-pass 2: V fp32 -> fp16 transposed + kv-pair packed ----
__global__ void convert_v_kernel(const float* __restrict__ v)
{
    __shared__ float vs[64][129];
    const int kt = blockIdx.x, kvh = blockIdx.y, nkt = gridDim.x;
    const int tid = threadIdx.x;

    #pragma unroll
    for (int it = 0; it < 16; ++it) {
        const int idx = tid + it * 128;
        const int row = idx >> 5, f4 = idx & 31;
        float4 val = *reinterpret_cast<const float4*>(
            v + ((size_t)((kt * 64 + row) * NKVH + kvh)) * HD + f4 * 4);
        vs[row][f4 * 4 + 0] = val.x; vs[row][f4 * 4 + 1] = val.y;
        vs[row][f4 * 4 + 2] = val.z; vs[row][f4 * 4 + 3] = val.w;
    }
    __syncthreads();

    const int d = tid;
    uint32_t* outp = VT_g + ((size_t)(kvh * nkt + kt) * HD + d) * 32;
    #pragma unroll
    for (int p = 0; p < 32; ++p)
        outp[p] = pack_f16x2(vs[2 * p][d], vs[2 * p + 1][d]);
}

extern __shared__ unsigned char smem_raw[];

__global__ __launch_bounds__(128, 2)
void attn_mma_kernel(const float* __restrict__ q, float* __restrict__ out, int seq)
{
    const uint32_t sb  = smem_u32(smem_raw);
    const uint32_t q_b = sb + SM_Q;
    const uint32_t k_b[2] = { sb + SM_K0, sb + SM_K1 };
    const uint32_t v_b[2] = { sb + SM_V0, sb + SM_V1 };

    const int tid  = threadIdx.x;
    const int lane = tid & 31;
    const int wid  = tid >> 5;           // warp owns rows wid*32 .. wid*32+31
    const int g    = lane >> 2;
    const int tg   = lane & 3;

    const int qt  = (gridDim.x - 1) - blockIdx.x;   // heavy blocks first
    const int hh  = blockIdx.y;
    const int kvh = hh >> 2;
    const int q0  = qt * BM;
    const int nkt = seq >> 6;                       // 64-wide kv tiles total
    const int nkt_this = (qt + 1) * (BM / BN);      // kv tiles needed

    // fill coords
    const int f_kv = tid >> 1;
    const int f_dp = (tid & 1) * 32;

    // ---- Q fill (once): fp32 gmem -> fp16 smem, scale*log2e folded ----
    {
        const float4* gq = reinterpret_cast<const float4*>(
            q + ((size_t)(q0 + tid) * NH + hh) * HD);
        const float sc = QK_SCALE * LOG2E;
        #pragma unroll
        for (int j = 0; j < 32; ++j) {
            float4 val = gq[j];
            const uint32_t off = (uint32_t)(tid * QKSTR + j * 2) * 4u;
            STSV2(q_b + off, pack_f16x2(val.x * sc, val.y * sc),
                             pack_f16x2(val.z * sc, val.w * sc));
        }
    }

    // ---- async prefetch of K/V tile kt into buffer bsel ----
    auto prefetch_kv = [&](int kt, int bsel) {
        const uint32_t* srcK =
            Kh_g + ((size_t)(kt * BN + f_kv) * NKVH + kvh) * 64 + f_dp;
        const uint32_t dstK = k_b[bsel] + (uint32_t)(f_kv * QKSTR + f_dp) * 4u;
        #pragma unroll
        for (int j = 0; j < 8; ++j)
            CPASYNC16(dstK + j * 16u, srcK + j * 4);
        const uint32_t* srcV =
            VT_g + ((size_t)(kvh * nkt + kt) * HD + tid) * 32;
        const uint32_t dstV = v_b[bsel] + (uint32_t)(tid * VSTR) * 4u;
        #pragma unroll
        for (int j = 0; j < 8; ++j)
            CPASYNC16(dstV + j * 16u, srcV + j * 4);
    };

    prefetch_kv(0, 0);
    CPASYNC_COMMIT();

    // Per-thread rows: mt in {0,1}, hb in {0,1} -> row wid*32 + mt*16 + g + hb*8
    float m_s[2][2] = { { -INFINITY, -INFINITY }, { -INFINITY, -INFINITY } };
    float l_s[2][2] = { { 0.f, 0.f }, { 0.f, 0.f } };
    float o[2][16][4];
    #pragma unroll
    for (int mt = 0; mt < 2; ++mt)
        #pragma unroll
        for (int nt = 0; nt < 16; ++nt)
            #pragma unroll
            for (int j = 0; j < 4; ++j) o[mt][nt][j] = 0.f;

    for (int kt = 0; kt < nkt_this; ++kt) {
        CPASYNC_WAIT0();     // tile kt copy complete (this thread)
        __syncthreads();     // all threads' copies visible; prev compute done

        // overlap: start copying tile kt+1 into the other buffer
        if (kt + 1 < nkt_this) {
            prefetch_kv(kt + 1, (kt + 1) & 1);
            CPASYNC_COMMIT();
        }
        const uint32_t kb = k_b[kt & 1];
        const uint32_t vb = v_b[kt & 1];

        // ---- gemm1: S = Q * K^T (fp16, warp: 32x64) ----
        float c1[2][8][4];
        #pragma unroll
        for (int mt = 0; mt < 2; ++mt)
            #pragma unroll
            for (int nt = 0; nt < 8; ++nt)
                #pragma unroll
                for (int j = 0; j < 4; ++j) c1[mt][nt][j] = 0.f;

        #pragma unroll
        for (int kc = 0; kc < 8; ++kc) {
            uint32_t aH[2][4], bH[8][2];
            #pragma unroll
            for (int mt = 0; mt < 2; ++mt) {
                const uint32_t offA = (uint32_t)((wid * 32 + mt * 16 + (lane & 15)) * QKSTR
                                                 + kc * 8 + (lane >> 4) * 4) * 4u;
                LDMX4(aH[mt], q_b + offA);
            }
            #pragma unroll
            for (int t = 0; t < 4; ++t) {
                const uint32_t offB = (uint32_t)((t * 16 + ((lane >> 4) & 1) * 8 + (lane & 7)) * QKSTR
                                                 + kc * 8 + ((lane >> 3) & 1) * 4) * 4u;
                uint32_t rh[4];
                LDMX4(rh, kb + offB);
                bH[2*t][0] = rh[0]; bH[2*t][1] = rh[1]; bH[2*t+1][0] = rh[2]; bH[2*t+1][1] = rh[3];
            }
            #pragma unroll
            for (int mt = 0; mt < 2; ++mt)
                #pragma unroll
                for (int nt = 0; nt < 8; ++nt)
                    MMA_F16(c1[mt][nt], aH[mt], bH[nt]);
        }

        // ---- mask (partial tiles) + online softmax (rows warp-local) ----
        const bool need_mask = (kt * BN + BN - 1) > (q0 + wid * 32);
        #pragma unroll
        for (int mt = 0; mt < 2; ++mt) {
            #pragma unroll
            for (int hb = 0; hb < 2; ++hb) {
                const int qi = q0 + wid * 32 + mt * 16 + g + hb * 8;
                if (need_mask) {
                    #pragma unroll
                    for (int nt = 0; nt < 8; ++nt) {
                        const int kj = kt * BN + nt * 8 + 2 * tg;
                        if (kj + 0 > qi) c1[mt][nt][hb * 2 + 0] = -INFINITY;
                        if (kj + 1 > qi) c1[mt][nt][hb * 2 + 1] = -INFINITY;
                    }
                }
                float mx = -INFINITY;
                #pragma unroll
                for (int nt = 0; nt < 8; ++nt)
                    mx = fmaxf(mx, fmaxf(c1[mt][nt][hb * 2], c1[mt][nt][hb * 2 + 1]));
                mx = fmaxf(mx, __shfl_xor_sync(0xffffffffu, mx, 1));
                mx = fmaxf(mx, __shfl_xor_sync(0xffffffffu, mx, 2));

                const float m_new = fmaxf(m_s[mt][hb], mx);   // finite: col<=row exists
                const bool  grew  = m_new > m_s[mt][hb];
                const float alpha = ex2(m_s[mt][hb] - m_new);  // ==1.0 when !grew
                m_s[mt][hb] = m_new;

                float rs = 0.f;
                #pragma unroll
                for (int nt = 0; nt < 8; ++nt) {
                    float p0 = ex2(c1[mt][nt][hb * 2 + 0] - m_new);
                    float p1 = ex2(c1[mt][nt][hb * 2 + 1] - m_new);
                    c1[mt][nt][hb * 2 + 0] = p0;
                    c1[mt][nt][hb * 2 + 1] = p1;
                    rs += p0 + p1;
                }
                rs += __shfl_xor_sync(0xffffffffu, rs, 1);
                rs += __shfl_xor_sync(0xffffffffu, rs, 2);

                // Warp-uniform rescale skip: if no lane's max grew, alpha==1.0
                // exactly for every lane -> skipping is bit-identical.
                if (__any_sync(0xffffffffu, grew)) {
                    l_s[mt][hb] = l_s[mt][hb] * alpha + rs;
                    #pragma unroll
                    for (int nt = 0; nt < 16; ++nt) {
                        o[mt][nt][hb * 2 + 0] *= alpha;
                        o[mt][nt][hb * 2 + 1] *= alpha;
                    }
                } else {
                    l_s[mt][hb] = l_s[mt][hb] * alpha + rs;   // alpha==1.0 (exact)
                }
            }
        }

        // ---- gemm2: O += P V. P packed from c1 registers; V frags shared by mt ----
        #pragma unroll
        for (int kc = 0; kc < 4; ++kc) {
            uint32_t aP[2][4];
            #pragma unroll
            for (int mt = 0; mt < 2; ++mt) {
                aP[mt][0] = pack_f16x2(c1[mt][2*kc+0][0], c1[mt][2*kc+0][1]);
                aP[mt][1] = pack_f16x2(c1[mt][2*kc+0][2], c1[mt][2*kc+0][3]);
                aP[mt][2] = pack_f16x2(c1[mt][2*kc+1][0], c1[mt][2*kc+1][1]);
                aP[mt][3] = pack_f16x2(c1[mt][2*kc+1][2], c1[mt][2*kc+1][3]);
            }
            #pragma unroll
            for (int t = 0; t < 8; ++t) {
                const uint32_t offV = (uint32_t)((t * 16 + ((lane >> 4) & 1) * 8 + (lane & 7)) * VSTR
                                                 + kc * 8 + ((lane >> 3) & 1) * 4) * 4u;
                uint32_t rv[4];
                LDMX4(rv, vb + offV);
                uint32_t b0[2] = { rv[0], rv[1] }, b1[2] = { rv[2], rv[3] };
                #pragma unroll
                for (int mt = 0; mt < 2; ++mt) {
                    MMA_F16(o[mt][2 * t + 0], aP[mt], b0);
                    MMA_F16(o[mt][2 * t + 1], aP[mt], b1);
                }
            }
        }
    }

    // ---- Epilogue: normalize, store ----
    #pragma unroll
    for (int mt = 0; mt < 2; ++mt)
        #pragma unroll
        for (int hb = 0; hb < 2; ++hb) {
            const float inv = 1.f / l_s[mt][hb];
            const int grow = q0 + wid * 32 + mt * 16 + g + hb * 8;
            float* obase = out + ((size_t)grow * NH + hh) * HD + 2 * tg;
            #pragma unroll
            for (int nt = 0; nt < 16; ++nt) {
                float2 val = make_float2(o[mt][nt][hb * 2 + 0] * inv,
                                         o[mt][nt][hb * 2 + 1] * inv);
                *reinterpret_cast<float2*>(obase + nt * 8) = val;
            }
        }
}

extern "C" void kernel_launch(void* const* d_in, const int* in_sizes, int n_in,
                              void* d_out, int out_size)
{
    const float* q = (const float*)d_in[0];
    const float* k = (const float*)d_in[1];
    const float* v = (const float*)d_in[2];
    float* out = (float*)d_out;

    const int seq = in_sizes[0] / (NH * HD);

    const int n_pairs = seq * NKVH * 64;
    convert_k_kernel<<<(n_pairs + 255) / 256, 256>>>(k, n_pairs);
    convert_v_kernel<<<dim3(seq / BN, NKVH), 128>>>(v);

    cudaFuncSetAttribute(attn_mma_kernel,
                         cudaFuncAttributeMaxDynamicSharedMemorySize, SMEM_BYTES);

    dim3 grid(seq / BM, NH);
    attn_mma_kernel<<<grid, 128, SMEM_BYTES>>>(q, out, seq);
}

// round 16
// speedup vs baseline: 1.0567x; 1.0487x over previous
#include <cuda_runtime.h>
#include <cuda_fp16.h>
#include <cstdint>
#include <math.h>

// Causal GQA attention prefill, S=2048, H=32, KVH=8, D=128, fp32 I/O.
// Pure fp16 mma.sync. Pre-pass converts K/V to fp16 (V transposed+packed).
// BM=128, 32 rows/warp. P in registers. cp.async.cg double-buffered K/V:
// copy of tile kt+1 overlaps compute of tile kt; one barrier per iteration.
// R16 main kernel is byte-exact R12 (best measured: 240.7us) — A/A re-bench
// after three bit-identical micro-edits each measured slower; convert_k
// vectorized (isolated change).

#define NH    32
#define NKVH  8
#define HD    128
#define BM    128
#define BN    64
#define SMAX  2048
#define QK_SCALE 0.08838834764831845f
#define LOG2E    1.4426950408889634f

#define QKSTR 68   // Q/K row stride in u32 words (64 data + 4 pad)
#define VSTR  36   // VT row stride in u32 words (32 data + 4 pad)

#define SM_Q  0                       // Q  [128][68] u32 = 34816 B
#define SM_K0 34816                   // K0 [64][68]  u32 = 17408 B
#define SM_K1 52224                   // K1
#define SM_V0 69632                   // V0 [128][36] u32 = 18432 B
#define SM_V1 88064                   // V1
#define SMEM_BYTES 106496

// fp16 scratch (pre-converted). K: [s][kvh][64 d-pairs]. V: [kvh][kt][d][32 kv-pairs].
__device__ uint32_t Kh_g[SMAX * NKVH * 64];
__device__ uint32_t VT_g[NKVH * (SMAX / BN) * HD * 32];

__device__ __forceinline__ uint32_t smem_u32(const void* p) {
    uint32_t a;
    asm("{ .reg .u64 t; cvta.to.shared.u64 t, %1; cvt.u32.u64 %0, t; }" : "=r"(a) : "l"(p));
    return a;
}
__device__ __forceinline__ float ex2(float x) {
    float r; asm("ex2.approx.f32 %0, %1;" : "=f"(r) : "f"(x)); return r;
}
__device__ __forceinline__ uint32_t pack_f16x2(float lo, float hi) {
    uint32_t r; asm("cvt.rn.f16x2.f32 %0, %1, %2;" : "=r"(r) : "f"(hi), "f"(lo)); return r;
}

#define MMA_F16(c, a, b) \
    asm volatile("mma.sync.aligned.m16n8k16.row.col.f32.f16.f16.f32 " \
                 "{%0,%1,%2,%3},{%4,%5,%6,%7},{%8,%9},{%0,%1,%2,%3};" \
        : "+f"((c)[0]), "+f"((c)[1]), "+f"((c)[2]), "+f"((c)[3]) \
        : "r"((a)[0]), "r"((a)[1]), "r"((a)[2]), "r"((a)[3]), "r"((b)[0]), "r"((b)[1]))

#define LDMX4(r, addr) \
    asm volatile("ldmatrix.sync.aligned.m8n8.x4.shared.b16 {%0,%1,%2,%3}, [%4];" \
        : "=r"((r)[0]), "=r"((r)[1]), "=r"((r)[2]), "=r"((r)[3]) : "r"(addr))

#define STSV2(addr, r0, r1) \
    asm volatile("st.shared.v2.b32 [%0], {%1,%2};" :: "r"(addr), "r"(r0), "r"(r1) : "memory")

#define CPASYNC16(dst, src) \
    asm volatile("cp.async.cg.shared.global [%0], [%1], 16;" :: "r"(dst), "l"(src) : "memory")
#define CPASYNC_COMMIT() asm volatile("cp.async.commit_group;" ::: "memory")
#define CPASYNC_WAIT0()  asm volatile("cp.async.wait_group 0;" ::: "memory")

// ---- pre-pass 1: K fp32 -> fp16 packed (float4 vectorized, coalesced) ----
__global__ void convert_k_kernel(const float4* __restrict__ k4, int n4)
{
    int i = blockIdx.x * blockDim.x + threadIdx.x;
    if (i < n4) {
        float4 val = k4[i];
        uint2 r = make_uint2(pack_f16x2(val.x, val.y), pack_f16x2(val.z, val.w));
        reinterpret_cast<uint2*>(Kh_g)[i] = r;
    }
}

// ---- pre-pass 2: V fp32 -> fp16 transposed + kv-pair packed ----
__global__ void convert_v_kernel(const float* __restrict__ v)
{
    __shared__ float vs[64][129];
    const int kt = blockIdx.x, kvh = blockIdx.y, nkt = gridDim.x;
    const int tid = threadIdx.x;

    #pragma unroll
    for (int it = 0; it < 16; ++it) {
        const int idx = tid + it * 128;
        const int row = idx >> 5, f4 = idx & 31;
        float4 val = *reinterpret_cast<const float4*>(
            v + ((size_t)((kt * 64 + row) * NKVH + kvh)) * HD + f4 * 4);
        vs[row][f4 * 4 + 0] = val.x; vs[row][f4 * 4 + 1] = val.y;
        vs[row][f4 * 4 + 2] = val.z; vs[row][f4 * 4 + 3] = val.w;
    }
    __syncthreads();

    const int d = tid;
    uint32_t* outp = VT_g + ((size_t)(kvh * nkt + kt) * HD + d) * 32;
    #pragma unroll
    for (int p = 0; p < 32; ++p)
        outp[p] = pack_f16x2(vs[2 * p][d], vs[2 * p + 1][d]);
}

extern __shared__ unsigned char smem_raw[];

__global__ __launch_bounds__(128, 2)
void attn_mma_kernel(const float* __restrict__ q, float* __restrict__ out, int seq)
{
    const uint32_t sb  = smem_u32(smem_raw);
    const uint32_t q_b = sb + SM_Q;
    const uint32_t k_b[2] = { sb + SM_K0, sb + SM_K1 };
    const uint32_t v_b[2] = { sb + SM_V0, sb + SM_V1 };

    const int tid  = threadIdx.x;
    const int lane = tid & 31;
    const int wid  = tid >> 5;           // warp owns rows wid*32 .. wid*32+31
    const int g    = lane >> 2;
    const int tg   = lane & 3;

    const int qt  = (gridDim.x - 1) - blockIdx.x;   // heavy blocks first
    const int hh  = blockIdx.y;
    const int kvh = hh >> 2;
    const int q0  = qt * BM;
    const int nkt = seq >> 6;                       // 64-wide kv tiles total
    const int nkt_this = (qt + 1) * (BM / BN);      // kv tiles needed

    // fill coords
    const int f_kv = tid >> 1;
    const int f_dp = (tid & 1) * 32;

    // ---- Q fill (once): fp32 gmem -> fp16 smem, scale*log2e folded ----
    {
        const float4* gq = reinterpret_cast<const float4*>(
            q + ((size_t)(q0 + tid) * NH + hh) * HD);
        const float sc = QK_SCALE * LOG2E;
        #pragma unroll
        for (int j = 0; j < 32; ++j) {
            float4 val = gq[j];
            const uint32_t off = (uint32_t)(tid * QKSTR + j * 2) * 4u;
            STSV2(q_b + off, pack_f16x2(val.x * sc, val.y * sc),
                             pack_f16x2(val.z * sc, val.w * sc));
        }
    }

    // ---- async prefetch of K/V tile kt into buffer bsel ----
    auto prefetch_kv = [&](int kt, int bsel) {
        const uint32_t* srcK =
            Kh_g + ((size_t)(kt * BN + f_kv) * NKVH + kvh) * 64 + f_dp;
        const uint32_t dstK = k_b[bsel] + (uint32_t)(f_kv * QKSTR + f_dp) * 4u;
        #pragma unroll
        for (int j = 0; j < 8; ++j)
            CPASYNC16(dstK + j * 16u, srcK + j * 4);
        const uint32_t* srcV =
            VT_g + ((size_t)(kvh * nkt + kt) * HD + tid) * 32;
        const uint32_t dstV = v_b[bsel] + (uint32_t)(tid * VSTR) * 4u;
        #pragma unroll
        for (int j = 0; j < 8; ++j)
            CPASYNC16(dstV + j * 16u, srcV + j * 4);
    };

    prefetch_kv(0, 0);
    CPASYNC_COMMIT();

    // Per-thread rows: mt in {0,1}, hb in {0,1} -> row wid*32 + mt*16 + g + hb*8
    float m_s[2][2] = { { -INFINITY, -INFINITY }, { -INFINITY, -INFINITY } };
    float l_s[2][2] = { { 0.f, 0.f }, { 0.f, 0.f } };
    float o[2][16][4];
    #pragma unroll
    for (int mt = 0; mt < 2; ++mt)
        #pragma unroll
        for (int nt = 0; nt < 16; ++nt)
            #pragma unroll
            for (int j = 0; j < 4; ++j) o[mt][nt][j] = 0.f;

    for (int kt = 0; kt < nkt_this; ++kt) {
        CPASYNC_WAIT0();     // tile kt copy complete (this thread)
        __syncthreads();     // all threads' copies visible; prev compute done

        // overlap: start copying tile kt+1 into the other buffer
        if (kt + 1 < nkt_this) {
            prefetch_kv(kt + 1, (kt + 1) & 1);
            CPASYNC_COMMIT();
        }
        const uint32_t kb = k_b[kt & 1];
        const uint32_t vb = v_b[kt & 1];

        // ---- gemm1: S = Q * K^T (fp16, warp: 32x64) ----
        float c1[2][8][4];
        #pragma unroll
        for (int mt = 0; mt < 2; ++mt)
            #pragma unroll
            for (int nt = 0; nt < 8; ++nt)
                #pragma unroll
                for (int j = 0; j < 4; ++j) c1[mt][nt][j] = 0.f;

        #pragma unroll
        for (int kc = 0; kc < 8; ++kc) {
            uint32_t aH[2][4], bH[8][2];
            #pragma unroll
            for (int mt = 0; mt < 2; ++mt) {
                const uint32_t offA = (uint32_t)((wid * 32 + mt * 16 + (lane & 15)) * QKSTR
                                                 + kc * 8 + (lane >> 4) * 4) * 4u;
                LDMX4(aH[mt], q_b + offA);
            }
            #pragma unroll
            for (int t = 0; t < 4; ++t) {
                const uint32_t offB = (uint32_t)((t * 16 + ((lane >> 4) & 1) * 8 + (lane & 7)) * QKSTR
                                                 + kc * 8 + ((lane >> 3) & 1) * 4) * 4u;
                uint32_t rh[4];
                LDMX4(rh, kb + offB);
                bH[2*t][0] = rh[0]; bH[2*t][1] = rh[1]; bH[2*t+1][0] = rh[2]; bH[2*t+1][1] = rh[3];
            }
            #pragma unroll
            for (int mt = 0; mt < 2; ++mt)
                #pragma unroll
                for (int nt = 0; nt < 8; ++nt)
                    MMA_F16(c1[mt][nt], aH[mt], bH[nt]);
        }

        // ---- mask (partial tiles) + online softmax (rows warp-local) ----
        const bool need_mask = (kt * BN + BN - 1) > (q0 + wid * 32);
        #pragma unroll
        for (int mt = 0; mt < 2; ++mt) {
            #pragma unroll
            for (int hb = 0; hb < 2; ++hb) {
                const int qi = q0 + wid * 32 + mt * 16 + g + hb * 8;
                if (need_mask) {
                    #pragma unroll
                    for (int nt = 0; nt < 8; ++nt) {
                        const int kj = kt * BN + nt * 8 + 2 * tg;
                        if (kj + 0 > qi) c1[mt][nt][hb * 2 + 0] = -INFINITY;
                        if (kj + 1 > qi) c1[mt][nt][hb * 2 + 1] = -INFINITY;
                    }
                }
                float mx = -INFINITY;
                #pragma unroll
                for (int nt = 0; nt < 8; ++nt)
                    mx = fmaxf(mx, fmaxf(c1[mt][nt][hb * 2], c1[mt][nt][hb * 2 + 1]));
                mx = fmaxf(mx, __shfl_xor_sync(0xffffffffu, mx, 1));
                mx = fmaxf(mx, __shfl_xor_sync(0xffffffffu, mx, 2));

                const float m_new = fmaxf(m_s[mt][hb], mx);   // finite: col<=row exists
                const float alpha = ex2(m_s[mt][hb] - m_new);
                m_s[mt][hb] = m_new;

                float rs = 0.f;
                #pragma unroll
                for (int nt = 0; nt < 8; ++nt) {
                    float p0 = ex2(c1[mt][nt][hb * 2 + 0] - m_new);
                    float p1 = ex2(c1[mt][nt][hb * 2 + 1] - m_new);
                    c1[mt][nt][hb * 2 + 0] = p0;
                    c1[mt][nt][hb * 2 + 1] = p1;
                    rs += p0 + p1;
                }
                rs += __shfl_xor_sync(0xffffffffu, rs, 1);
                rs += __shfl_xor_sync(0xffffffffu, rs, 2);
                l_s[mt][hb] = l_s[mt][hb] * alpha + rs;

                #pragma unroll
                for (int nt = 0; nt < 16; ++nt) {
                    o[mt][nt][hb * 2 + 0] *= alpha;
                    o[mt][nt][hb * 2 + 1] *= alpha;
                }
            }
        }

        // ---- gemm2: O += P V. P packed from c1 registers; V frags shared by mt ----
        #pragma unroll
        for (int kc = 0; kc < 4; ++kc) {
            uint32_t aP[2][4];
            #pragma unroll
            for (int mt = 0; mt < 2; ++mt) {
                aP[mt][0] = pack_f16x2(c1[mt][2*kc+0][0], c1[mt][2*kc+0][1]);
                aP[mt][1] = pack_f16x2(c1[mt][2*kc+0][2], c1[mt][2*kc+0][3]);
                aP[mt][2] = pack_f16x2(c1[mt][2*kc+1][0], c1[mt][2*kc+1][1]);
                aP[mt][3] = pack_f16x2(c1[mt][2*kc+1][2], c1[mt][2*kc+1][3]);
            }
            #pragma unroll
            for (int t = 0; t < 8; ++t) {
                const uint32_t offV = (uint32_t)((t * 16 + ((lane >> 4) & 1) * 8 + (lane & 7)) * VSTR
                                                 + kc * 8 + ((lane >> 3) & 1) * 4) * 4u;
                uint32_t rv[4];
                LDMX4(rv, vb + offV);
                uint32_t b0[2] = { rv[0], rv[1] }, b1[2] = { rv[2], rv[3] };
                #pragma unroll
                for (int mt = 0; mt < 2; ++mt) {
                    MMA_F16(o[mt][2 * t + 0], aP[mt], b0);
                    MMA_F16(o[mt][2 * t + 1], aP[mt], b1);
                }
            }
        }
    }

    // ---- Epilogue: normalize, store ----
    #pragma unroll
    for (int mt = 0; mt < 2; ++mt)
        #pragma unroll
        for (int hb = 0; hb < 2; ++hb) {
            const float inv = 1.f / l_s[mt][hb];
            const int grow = q0 + wid * 32 + mt * 16 + g + hb * 8;
            float* obase = out + ((size_t)grow * NH + hh) * HD + 2 * tg;
            #pragma unroll
            for (int nt = 0; nt < 16; ++nt) {
                float2 val = make_float2(o[mt][nt][hb * 2 + 0] * inv,
                                         o[mt][nt][hb * 2 + 1] * inv);
                *reinterpret_cast<float2*>(obase + nt * 8) = val;
            }
        }
}

extern "C" void kernel_launch(void* const* d_in, const int* in_sizes, int n_in,
                              void* d_out, int out_size)
{
    const float* q = (const float*)d_in[0];
    const float* k = (const float*)d_in[1];
    const float* v = (const float*)d_in[2];
    float* out = (float*)d_out;

    const int seq = in_sizes[0] / (NH * HD);

    const int n4 = seq * NKVH * 32;    // float4 count = elems / 4
    convert_k_kernel<<<(n4 + 255) / 256, 256>>>((const float4*)k, n4);
    convert_v_kernel<<<dim3(seq / BN, NKVH), 128>>>(v);

    cudaFuncSetAttribute(attn_mma_kernel,
                         cudaFuncAttributeMaxDynamicSharedMemorySize, SMEM_BYTES);

    dim3 grid(seq / BM, NH);
    attn_mma_kernel<<<grid, 128, SMEM_BYTES>>>(q, out, seq);
}

// round 17
// speedup vs baseline: 1.4764x; 1.3971x over previous
#include <cuda_runtime.h>
#include <cuda_fp16.h>
#include <cstdint>
#include <math.h>

// Causal GQA attention prefill, S=2048, H=32, KVH=8, D=128, fp32 I/O.
// Pure fp16 mma.sync. Pre-pass converts K/V to fp16 (V transposed+packed).
// BM=128, 32 rows/warp. P in registers. cp.async.cg double-buffered K/V.
// R17: hot loop byte-identical to R12/R16. Changes OUTSIDE the loop only:
//  (1) 1D grid in global work-descending order (all heavy CTAs dispatch first
//      -> wave-2 tail is 1-tile CTAs instead of 16-tile CTAs),
//  (2) convert_v uses uint4 vectorized writes.

#define NH    32
#define NKVH  8
#define HD    128
#define BM    128
#define BN    64
#define SMAX  2048
#define QK_SCALE 0.08838834764831845f
#define LOG2E    1.4426950408889634f

#define QKSTR 68   // Q/K row stride in u32 words (64 data + 4 pad)
#define VSTR  36   // VT row stride in u32 words (32 data + 4 pad)

#define SM_Q  0                       // Q  [128][68] u32 = 34816 B
#define SM_K0 34816                   // K0 [64][68]  u32 = 17408 B
#define SM_K1 52224                   // K1
#define SM_V0 69632                   // V0 [128][36] u32 = 18432 B
#define SM_V1 88064                   // V1
#define SMEM_BYTES 106496

// fp16 scratch (pre-converted). K: [s][kvh][64 d-pairs]. V: [kvh][kt][d][32 kv-pairs].
__device__ uint32_t Kh_g[SMAX * NKVH * 64];
__device__ uint32_t VT_g[NKVH * (SMAX / BN) * HD * 32];

__device__ __forceinline__ uint32_t smem_u32(const void* p) {
    uint32_t a;
    asm("{ .reg .u64 t; cvta.to.shared.u64 t, %1; cvt.u32.u64 %0, t; }" : "=r"(a) : "l"(p));
    return a;
}
__device__ __forceinline__ float ex2(float x) {
    float r; asm("ex2.approx.f32 %0, %1;" : "=f"(r) : "f"(x)); return r;
}
__device__ __forceinline__ uint32_t pack_f16x2(float lo, float hi) {
    uint32_t r; asm("cvt.rn.f16x2.f32 %0, %1, %2;" : "=r"(r) : "f"(hi), "f"(lo)); return r;
}

#define MMA_F16(c, a, b) \
    asm volatile("mma.sync.aligned.m16n8k16.row.col.f32.f16.f16.f32 " \
                 "{%0,%1,%2,%3},{%4,%5,%6,%7},{%8,%9},{%0,%1,%2,%3};" \
        : "+f"((c)[0]), "+f"((c)[1]), "+f"((c)[2]), "+f"((c)[3]) \
        : "r"((a)[0]), "r"((a)[1]), "r"((a)[2]), "r"((a)[3]), "r"((b)[0]), "r"((b)[1]))

#define LDMX4(r, addr) \
    asm volatile("ldmatrix.sync.aligned.m8n8.x4.shared.b16 {%0,%1,%2,%3}, [%4];" \
        : "=r"((r)[0]), "=r"((r)[1]), "=r"((r)[2]), "=r"((r)[3]) : "r"(addr))

#define STSV2(addr, r0, r1) \
    asm volatile("st.shared.v2.b32 [%0], {%1,%2};" :: "r"(addr), "r"(r0), "r"(r1) : "memory")

#define CPASYNC16(dst, src) \
    asm volatile("cp.async.cg.shared.global [%0], [%1], 16;" :: "r"(dst), "l"(src) : "memory")
#define CPASYNC_COMMIT() asm volatile("cp.async.commit_group;" ::: "memory")
#define CPASYNC_WAIT0()  asm volatile("cp.async.wait_group 0;" ::: "memory")

// ---- pre-pass 1: K fp32 -> fp16 packed (float4 vectorized, coalesced) ----
__global__ void convert_k_kernel(const float4* __restrict__ k4, int n4)
{
    int i = blockIdx.x * blockDim.x + threadIdx.x;
    if (i < n4) {
        float4 val = k4[i];
        uint2 r = make_uint2(pack_f16x2(val.x, val.y), pack_f16x2(val.z, val.w));
        reinterpret_cast<uint2*>(Kh_g)[i] = r;
    }
}

// ---- pre-pass 2: V fp32 -> fp16 transposed + kv-pair packed (uint4 stores) ----
__global__ void convert_v_kernel(const float* __restrict__ v)
{
    __shared__ float vs[64][129];
    const int kt = blockIdx.x, kvh = blockIdx.y, nkt = gridDim.x;
    const int tid = threadIdx.x;

    #pragma unroll
    for (int it = 0; it < 16; ++it) {
        const int idx = tid + it * 128;
        const int row = idx >> 5, f4 = idx & 31;
        float4 val = *reinterpret_cast<const float4*>(
            v + ((size_t)((kt * 64 + row) * NKVH + kvh)) * HD + f4 * 4);
        vs[row][f4 * 4 + 0] = val.x; vs[row][f4 * 4 + 1] = val.y;
        vs[row][f4 * 4 + 2] = val.z; vs[row][f4 * 4 + 3] = val.w;
    }
    __syncthreads();

    const int d = tid;
    uint4* outp = reinterpret_cast<uint4*>(
        VT_g + ((size_t)(kvh * nkt + kt) * HD + d) * 32);
    #pragma unroll
    for (int p4 = 0; p4 < 8; ++p4) {
        uint4 r;
        r.x = pack_f16x2(vs[8 * p4 + 0][d], vs[8 * p4 + 1][d]);
        r.y = pack_f16x2(vs[8 * p4 + 2][d], vs[8 * p4 + 3][d]);
        r.z = pack_f16x2(vs[8 * p4 + 4][d], vs[8 * p4 + 5][d]);
        r.w = pack_f16x2(vs[8 * p4 + 6][d], vs[8 * p4 + 7][d]);
        outp[p4] = r;
    }
}

extern __shared__ unsigned char smem_raw[];

__global__ __launch_bounds__(128, 2)
void attn_mma_kernel(const float* __restrict__ q, float* __restrict__ out, int seq)
{
    const uint32_t sb  = smem_u32(smem_raw);
    const uint32_t q_b = sb + SM_Q;
    const uint32_t k_b[2] = { sb + SM_K0, sb + SM_K1 };
    const uint32_t v_b[2] = { sb + SM_V0, sb + SM_V1 };

    const int tid  = threadIdx.x;
    const int lane = tid & 31;
    const int wid  = tid >> 5;           // warp owns rows wid*32 .. wid*32+31
    const int g    = lane >> 2;
    const int tg   = lane & 3;

    // Work-descending 1D schedule: blocks 0..31 are the heaviest (qt=nqt-1)
    // CTAs of each head, ..., last 32 blocks are the 1-tile CTAs.
    const int nqt = seq / BM;
    const int qt  = (nqt - 1) - (int)(blockIdx.x >> 5);
    const int hh  = (int)(blockIdx.x & 31);
    const int kvh = hh >> 2;
    const int q0  = qt * BM;
    const int nkt = seq >> 6;                       // 64-wide kv tiles total
    const int nkt_this = (qt + 1) * (BM / BN);      // kv tiles needed

    // fill coords
    const int f_kv = tid >> 1;
    const int f_dp = (tid & 1) * 32;

    // ---- Q fill (once): fp32 gmem -> fp16 smem, scale*log2e folded ----
    {
        const float4* gq = reinterpret_cast<const float4*>(
            q + ((size_t)(q0 + tid) * NH + hh) * HD);
        const float sc = QK_SCALE * LOG2E;
        #pragma unroll
        for (int j = 0; j < 32; ++j) {
            float4 val = gq[j];
            const uint32_t off = (uint32_t)(tid * QKSTR + j * 2) * 4u;
            STSV2(q_b + off, pack_f16x2(val.x * sc, val.y * sc),
                             pack_f16x2(val.z * sc, val.w * sc));
        }
    }

    // ---- async prefetch of K/V tile kt into buffer bsel ----
    auto prefetch_kv = [&](int kt, int bsel) {
        const uint32_t* srcK =
            Kh_g + ((size_t)(kt * BN + f_kv) * NKVH + kvh) * 64 + f_dp;
        const uint32_t dstK = k_b[bsel] + (uint32_t)(f_kv * QKSTR + f_dp) * 4u;
        #pragma unroll
        for (int j = 0; j < 8; ++j)
            CPASYNC16(dstK + j * 16u, srcK + j * 4);
        const uint32_t* srcV =
            VT_g + ((size_t)(kvh * nkt + kt) * HD + tid) * 32;
        const uint32_t dstV = v_b[bsel] + (uint32_t)(tid * VSTR) * 4u;
        #pragma unroll
        for (int j = 0; j < 8; ++j)
            CPASYNC16(dstV + j * 16u, srcV + j * 4);
    };

    prefetch_kv(0, 0);
    CPASYNC_COMMIT();

    // Per-thread rows: mt in {0,1}, hb in {0,1} -> row wid*32 + mt*16 + g + hb*8
    float m_s[2][2] = { { -INFINITY, -INFINITY }, { -INFINITY, -INFINITY } };
    float l_s[2][2] = { { 0.f, 0.f }, { 0.f, 0.f } };
    float o[2][16][4];
    #pragma unroll
    for (int mt = 0; mt < 2; ++mt)
        #pragma unroll
        for (int nt = 0; nt < 16; ++nt)
            #pragma unroll
            for (int j = 0; j < 4; ++j) o[mt][nt][j] = 0.f;

    for (int kt = 0; kt < nkt_this; ++kt) {
        CPASYNC_WAIT0();     // tile kt copy complete (this thread)
        __syncthreads();     // all threads' copies visible; prev compute done

        // overlap: start copying tile kt+1 into the other buffer
        if (kt + 1 < nkt_this) {
            prefetch_kv(kt + 1, (kt + 1) & 1);
            CPASYNC_COMMIT();
        }
        const uint32_t kb = k_b[kt & 1];
        const uint32_t vb = v_b[kt & 1];

        // ---- gemm1: S = Q * K^T (fp16, warp: 32x64) ----
        float c1[2][8][4];
        #pragma unroll
        for (int mt = 0; mt < 2; ++mt)
            #pragma unroll
            for (int nt = 0; nt < 8; ++nt)
                #pragma unroll
                for (int j = 0; j < 4; ++j) c1[mt][nt][j] = 0.f;

        #pragma unroll
        for (int kc = 0; kc < 8; ++kc) {
            uint32_t aH[2][4], bH[8][2];
            #pragma unroll
            for (int mt = 0; mt < 2; ++mt) {
                const uint32_t offA = (uint32_t)((wid * 32 + mt * 16 + (lane & 15)) * QKSTR
                                                 + kc * 8 + (lane >> 4) * 4) * 4u;
                LDMX4(aH[mt], q_b + offA);
            }
            #pragma unroll
            for (int t = 0; t < 4; ++t) {
                const uint32_t offB = (uint32_t)((t * 16 + ((lane >> 4) & 1) * 8 + (lane & 7)) * QKSTR
                                                 + kc * 8 + ((lane >> 3) & 1) * 4) * 4u;
                uint32_t rh[4];
                LDMX4(rh, kb + offB);
                bH[2*t][0] = rh[0]; bH[2*t][1] = rh[1]; bH[2*t+1][0] = rh[2]; bH[2*t+1][1] = rh[3];
            }
            #pragma unroll
            for (int mt = 0; mt < 2; ++mt)
                #pragma unroll
                for (int nt = 0; nt < 8; ++nt)
                    MMA_F16(c1[mt][nt], aH[mt], bH[nt]);
        }

        // ---- mask (partial tiles) + online softmax (rows warp-local) ----
        const bool need_mask = (kt * BN + BN - 1) > (q0 + wid * 32);
        #pragma unroll
        for (int mt = 0; mt < 2; ++mt) {
            #pragma unroll
            for (int hb = 0; hb < 2; ++hb) {
                const int qi = q0 + wid * 32 + mt * 16 + g + hb * 8;
                if (need_mask) {
                    #pragma unroll
                    for (int nt = 0; nt < 8; ++nt) {
                        const int kj = kt * BN + nt * 8 + 2 * tg;
                        if (kj + 0 > qi) c1[mt][nt][hb * 2 + 0] = -INFINITY;
                        if (kj + 1 > qi) c1[mt][nt][hb * 2 + 1] = -INFINITY;
                    }
                }
                float mx = -INFINITY;
                #pragma unroll
                for (int nt = 0; nt < 8; ++nt)
                    mx = fmaxf(mx, fmaxf(c1[mt][nt][hb * 2], c1[mt][nt][hb * 2 + 1]));
                mx = fmaxf(mx, __shfl_xor_sync(0xffffffffu, mx, 1));
                mx = fmaxf(mx, __shfl_xor_sync(0xffffffffu, mx, 2));

                const float m_new = fmaxf(m_s[mt][hb], mx);   // finite: col<=row exists
                const float alpha = ex2(m_s[mt][hb] - m_new);
                m_s[mt][hb] = m_new;

                float rs = 0.f;
                #pragma unroll
                for (int nt = 0; nt < 8; ++nt) {
                    float p0 = ex2(c1[mt][nt][hb * 2 + 0] - m_new);
                    float p1 = ex2(c1[mt][nt][hb * 2 + 1] - m_new);
                    c1[mt][nt][hb * 2 + 0] = p0;
                    c1[mt][nt][hb * 2 + 1] = p1;
                    rs += p0 + p1;
                }
                rs += __shfl_xor_sync(0xffffffffu, rs, 1);
                rs += __shfl_xor_sync(0xffffffffu, rs, 2);
                l_s[mt][hb] = l_s[mt][hb] * alpha + rs;

                #pragma unroll
                for (int nt = 0; nt < 16; ++nt) {
                    o[mt][nt][hb * 2 + 0] *= alpha;
                    o[mt][nt][hb * 2 + 1] *= alpha;
                }
            }
        }

        // ---- gemm2: O += P V. P packed from c1 registers; V frags shared by mt ----
        #pragma unroll
        for (int kc = 0; kc < 4; ++kc) {
            uint32_t aP[2][4];
            #pragma unroll
            for (int mt = 0; mt < 2; ++mt) {
                aP[mt][0] = pack_f16x2(c1[mt][2*kc+0][0], c1[mt][2*kc+0][1]);
                aP[mt][1] = pack_f16x2(c1[mt][2*kc+0][2], c1[mt][2*kc+0][3]);
                aP[mt][2] = pack_f16x2(c1[mt][2*kc+1][0], c1[mt][2*kc+1][1]);
                aP[mt][3] = pack_f16x2(c1[mt][2*kc+1][2], c1[mt][2*kc+1][3]);
            }
            #pragma unroll
            for (int t = 0; t < 8; ++t) {
                const uint32_t offV = (uint32_t)((t * 16 + ((lane >> 4) & 1) * 8 + (lane & 7)) * VSTR
                                                 + kc * 8 + ((lane >> 3) & 1) * 4) * 4u;
                uint32_t rv[4];
                LDMX4(rv, vb + offV);
                uint32_t b0[2] = { rv[0], rv[1] }, b1[2] = { rv[2], rv[3] };
                #pragma unroll
                for (int mt = 0; mt < 2; ++mt) {
                    MMA_F16(o[mt][2 * t + 0], aP[mt], b0);
                    MMA_F16(o[mt][2 * t + 1], aP[mt], b1);
                }
            }
        }
    }

    // ---- Epilogue: normalize, store ----
    #pragma unroll
    for (int mt = 0; mt < 2; ++mt)
        #pragma unroll
        for (int hb = 0; hb < 2; ++hb) {
            const float inv = 1.f / l_s[mt][hb];
            const int grow = q0 + wid * 32 + mt * 16 + g + hb * 8;
            float* obase = out + ((size_t)grow * NH + hh) * HD + 2 * tg;
            #pragma unroll
            for (int nt = 0; nt < 16; ++nt) {
                float2 val = make_float2(o[mt][nt][hb * 2 + 0] * inv,
                                         o[mt][nt][hb * 2 + 1] * inv);
                *reinterpret_cast<float2*>(obase + nt * 8) = val;
            }
        }
}

extern "C" void kernel_launch(void* const* d_in, const int* in_sizes, int n_in,
                              void* d_out, int out_size)
{
    const float* q = (const float*)d_in[0];
    const float* k = (const float*)d_in[1];
    const float* v = (const float*)d_in[2];
    float* out = (float*)d_out;

    const int seq = in_sizes[0] / (NH * HD);

    const int n4 = seq * NKVH * 32;    // float4 count = elems / 4
    convert_k_kernel<<<(n4 + 255) / 256, 256>>>((const float4*)k, n4);
    convert_v_kernel<<<dim3(seq / BN, NKVH), 128>>>(v);

    cudaFuncSetAttribute(attn_mma_kernel,
                         cudaFuncAttributeMaxDynamicSharedMemorySize, SMEM_BYTES);

    // 1D grid, work-descending: block b -> (qt = nqt-1 - b/32, head = b%32)
    attn_mma_kernel<<<(seq / BM) * NH, 128, SMEM_BYTES>>>(q, out, seq);
}